// round 1
// baseline (speedup 1.0000x reference)
#include <cuda_runtime.h>
#include <cuda_bf16.h>

#define BB 32
#define TT 256
#define CC 512
#define LL 25
#define MM (BB*TT)   // 8192

// Scratch (device globals — no runtime allocation allowed)
__device__ float g_wf[(size_t)MM * CC];        // 16 MB: wf = X@W^T + b
__device__ float g_scores[(size_t)BB * LL * TT]; // softmax scores / attn

// ---------------------------------------------------------------------------
// Kernel 1: wf[m,n] = sum_k X[m,k] * W[n,k] + bias[n]
// Tiled fp32 SGEMM: BM=128, BN=64, BK=16, 256 threads, 8x4 per-thread tile.
// ---------------------------------------------------------------------------
__global__ __launch_bounds__(256) void k_gemm(const float* __restrict__ X,
                                              const float* __restrict__ W,
                                              const float* __restrict__ bias) {
    __shared__ __align__(16) float As[16][128];
    __shared__ __align__(16) float Bs[16][64];

    const int tid = threadIdx.x;
    const int tx = tid & 15;   // n direction (4 cols each)
    const int ty = tid >> 4;   // m direction (8 rows each)
    const int m0 = blockIdx.y * 128;
    const int n0 = blockIdx.x * 64;

    const int lr = tid >> 2;         // 0..63 (load row)
    const int lk = (tid & 3) * 4;    // k offset 0,4,8,12

    float acc[8][4];
#pragma unroll
    for (int i = 0; i < 8; i++)
#pragma unroll
        for (int j = 0; j < 4; j++) acc[i][j] = 0.f;

    for (int k0 = 0; k0 < CC; k0 += 16) {
#pragma unroll
        for (int r = 0; r < 2; r++) {
            int row = lr + r * 64;
            float4 v = *(const float4*)&X[(size_t)(m0 + row) * CC + k0 + lk];
            As[lk + 0][row] = v.x; As[lk + 1][row] = v.y;
            As[lk + 2][row] = v.z; As[lk + 3][row] = v.w;
        }
        {
            float4 v = *(const float4*)&W[(size_t)(n0 + lr) * CC + k0 + lk];
            Bs[lk + 0][lr] = v.x; Bs[lk + 1][lr] = v.y;
            Bs[lk + 2][lr] = v.z; Bs[lk + 3][lr] = v.w;
        }
        __syncthreads();
#pragma unroll
        for (int k = 0; k < 16; k++) {
            float4 a0 = *(const float4*)&As[k][ty * 8];
            float4 a1 = *(const float4*)&As[k][ty * 8 + 4];
            float4 bv = *(const float4*)&Bs[k][tx * 4];
            float a[8] = {a0.x, a0.y, a0.z, a0.w, a1.x, a1.y, a1.z, a1.w};
            float b[4] = {bv.x, bv.y, bv.z, bv.w};
#pragma unroll
            for (int i = 0; i < 8; i++)
#pragma unroll
                for (int j = 0; j < 4; j++) acc[i][j] += a[i] * b[j];
        }
        __syncthreads();
    }

    float4 bv = *(const float4*)&bias[n0 + tx * 4];
#pragma unroll
    for (int i = 0; i < 8; i++) {
        int m = m0 + ty * 8 + i;
        float4 o = make_float4(acc[i][0] + bv.x, acc[i][1] + bv.y,
                               acc[i][2] + bv.z, acc[i][3] + bv.w);
        *(float4*)&g_wf[(size_t)m * CC + n0 + tx * 4] = o;
    }
}

// ---------------------------------------------------------------------------
// Kernel 2: scores[b,l,t] = sum_c tanh(wf[b,t,c] + pos[l,c]) * aw[c]
// (atten_b dropped: softmax is shift-invariant)
// grid (B, T/32, 2): z splits L into 13+12 so pos tile fits static smem.
// Block = 8 warps; each warp handles 4 t's, lane covers 16 c's (4 float4s).
// ---------------------------------------------------------------------------
__device__ __forceinline__ float fast_tanh(float x) {
    x = fminf(15.f, fmaxf(-15.f, x));
    float e = __expf(2.f * x);
    return __fdividef(e - 1.f, e + 1.f);
}

__global__ __launch_bounds__(256) void k_scores(const float* __restrict__ pos,
                                                const float* __restrict__ aw) {
    __shared__ __align__(16) float sp[13 * CC];  // pos tile (<=13 rows)

    const int tid = threadIdx.x;
    const int b = blockIdx.x;
    const int tch = blockIdx.y;
    const int l0 = blockIdx.z * 13;
    const int nl = blockIdx.z ? 12 : 13;
    const int warp = tid >> 5, lane = tid & 31;

    for (int i = tid; i < nl * CC; i += 256) sp[i] = pos[l0 * CC + i];
    __syncthreads();

    float4 wv[4];
#pragma unroll
    for (int g = 0; g < 4; g++)
        wv[g] = *(const float4*)&aw[g * 128 + lane * 4];

    for (int tt = 0; tt < 4; tt++) {
        const int t = tch * 32 + warp * 4 + tt;
        const float* wrow = &g_wf[((size_t)b * TT + t) * CC];
        float4 fv[4];
#pragma unroll
        for (int g = 0; g < 4; g++)
            fv[g] = *(const float4*)&wrow[g * 128 + lane * 4];

        for (int l = 0; l < nl; l++) {
            float acc = 0.f;
#pragma unroll
            for (int g = 0; g < 4; g++) {
                float4 p = *(const float4*)&sp[l * CC + g * 128 + lane * 4];
                acc += fast_tanh(fv[g].x + p.x) * wv[g].x;
                acc += fast_tanh(fv[g].y + p.y) * wv[g].y;
                acc += fast_tanh(fv[g].z + p.z) * wv[g].z;
                acc += fast_tanh(fv[g].w + p.w) * wv[g].w;
            }
#pragma unroll
            for (int o = 16; o > 0; o >>= 1)
                acc += __shfl_xor_sync(0xFFFFFFFFu, acc, o);
            if (lane == 0)
                g_scores[((size_t)b * LL + l0 + l) * TT + t] = acc;
        }
    }
}

// ---------------------------------------------------------------------------
// Kernel 3: in-place softmax over t for each (b,l) row. 800 blocks x 256 thr.
// ---------------------------------------------------------------------------
__global__ __launch_bounds__(256) void k_softmax() {
    __shared__ float red[8];
    __shared__ float red2[8];
    const int row = blockIdx.x;
    float* s = g_scores + (size_t)row * TT;
    const int tid = threadIdx.x, lane = tid & 31, w = tid >> 5;

    float v = s[tid];
    float m = v;
#pragma unroll
    for (int o = 16; o > 0; o >>= 1)
        m = fmaxf(m, __shfl_xor_sync(0xFFFFFFFFu, m, o));
    if (lane == 0) red[w] = m;
    __syncthreads();
    float bm = red[0];
#pragma unroll
    for (int i = 1; i < 8; i++) bm = fmaxf(bm, red[i]);

    float e = __expf(v - bm);
    float sum = e;
#pragma unroll
    for (int o = 16; o > 0; o >>= 1)
        sum += __shfl_xor_sync(0xFFFFFFFFu, sum, o);
    if (lane == 0) red2[w] = sum;
    __syncthreads();
    float tot = 0.f;
#pragma unroll
    for (int i = 0; i < 8; i++) tot += red2[i];

    s[tid] = e / tot;
}

// ---------------------------------------------------------------------------
// Kernel 4: out[b,l,c] = sum_t attn[b,l,t] * wf[b,t,c]
// grid (C/128, B), 128 threads; attn tile for b in smem (25.6 KB).
// ---------------------------------------------------------------------------
__global__ __launch_bounds__(128) void k_pvam(float* __restrict__ out) {
    __shared__ float at[LL][TT];  // 25*256*4 = 25.6 KB
    const int b = blockIdx.y;
    const int c0 = blockIdx.x * 128;
    const int tid = threadIdx.x;

    for (int i = tid; i < LL * TT; i += 128)
        at[i / TT][i % TT] = g_scores[(size_t)b * LL * TT + i];
    __syncthreads();

    float acc[LL];
#pragma unroll
    for (int l = 0; l < LL; l++) acc[l] = 0.f;

    const float* wb = &g_wf[(size_t)b * TT * CC + c0 + tid];
#pragma unroll 4
    for (int t = 0; t < TT; t++) {
        float v = wb[(size_t)t * CC];
#pragma unroll
        for (int l = 0; l < LL; l++) acc[l] += at[l][t] * v;
    }
#pragma unroll
    for (int l = 0; l < LL; l++)
        out[((size_t)b * LL + l) * CC + c0 + tid] = acc[l];
}

// ---------------------------------------------------------------------------
extern "C" void kernel_launch(void* const* d_in, const int* in_sizes, int n_in,
                              void* d_out, int out_size) {
    const float* X    = (const float*)d_in[0];  // word_features (B,T,C)
    const float* W    = (const float*)d_in[1];  // word_fc_w (C,C)
    const float* bias = (const float*)d_in[2];  // word_fc_b (C,)
    const float* pos  = (const float*)d_in[3];  // pos_emb (L,C)
    const float* aw   = (const float*)d_in[4];  // atten_w (C,)
    // d_in[5] = atten_b: constant shift before softmax -> no effect; skipped.
    float* out = (float*)d_out;                 // (B,L,C) fp32

    dim3 g1(CC / 64, MM / 128);   // (8, 64)
    k_gemm<<<g1, 256>>>(X, W, bias);

    dim3 g2(BB, TT / 32, 2);      // (32, 8, 2)
    k_scores<<<g2, 256>>>(pos, aw);

    k_softmax<<<BB * LL, 256>>>();

    dim3 g4(CC / 128, BB);        // (4, 32)
    k_pvam<<<g4, 128>>>(out);
}

// round 4
// speedup vs baseline: 1.6234x; 1.6234x over previous
#include <cuda_runtime.h>
#include <cuda_bf16.h>
#include <cstdint>

#define BB 32
#define TT 256
#define CC 512
#define LL 25
#define MM (BB*TT)   // 8192

// Scratch (device globals — no runtime allocation allowed)
__device__ float g_wf[(size_t)MM * CC];            // 16 MB
__device__ float g_scores[(size_t)BB * LL * TT];   // 0.8 MB
__device__ float g_part[(size_t)4 * BB * LL * CC]; // 6.5 MB pvam partials

// ---------------------------------------------------------------------------
// Helpers
// ---------------------------------------------------------------------------
__device__ __forceinline__ uint32_t smem_u32(const void* p) {
    uint32_t a;
    asm("{ .reg .u64 t; cvta.to.shared.u64 t, %1; cvt.u32.u64 %0, t; }"
        : "=r"(a) : "l"(p));
    return a;
}
__device__ __forceinline__ void ldsm4(uint32_t* r, uint32_t addr) {
    asm volatile("ldmatrix.sync.aligned.m8n8.x4.shared.b16 {%0,%1,%2,%3}, [%4];"
                 : "=r"(r[0]), "=r"(r[1]), "=r"(r[2]), "=r"(r[3]) : "r"(addr));
}
__device__ __forceinline__ void mma16816(float* d, const uint32_t* a,
                                         uint32_t b0, uint32_t b1) {
    asm volatile(
        "mma.sync.aligned.m16n8k16.row.col.f32.bf16.bf16.f32 "
        "{%0,%1,%2,%3}, {%4,%5,%6,%7}, {%8,%9}, {%0,%1,%2,%3};"
        : "+f"(d[0]), "+f"(d[1]), "+f"(d[2]), "+f"(d[3])
        : "r"(a[0]), "r"(a[1]), "r"(a[2]), "r"(a[3]), "r"(b0), "r"(b1));
}
// fp32 -> bf16 hi + bf16 lo (residual), packed as bf16x2 words
__device__ __forceinline__ void cvt2(float4 v, uint2& hi, uint2& lo) {
    __nv_bfloat162 h01 = __floats2bfloat162_rn(v.x, v.y);
    __nv_bfloat162 h23 = __floats2bfloat162_rn(v.z, v.w);
    float2 f01 = __bfloat1622float2(h01);
    float2 f23 = __bfloat1622float2(h23);
    __nv_bfloat162 l01 = __floats2bfloat162_rn(v.x - f01.x, v.y - f01.y);
    __nv_bfloat162 l23 = __floats2bfloat162_rn(v.z - f23.x, v.w - f23.y);
    hi.x = *reinterpret_cast<uint32_t*>(&h01);
    hi.y = *reinterpret_cast<uint32_t*>(&h23);
    lo.x = *reinterpret_cast<uint32_t*>(&l01);
    lo.y = *reinterpret_cast<uint32_t*>(&l23);
}

// ---------------------------------------------------------------------------
// Kernel 1: wf = X @ W^T + bias via mma.sync bf16 with hi/lo split (3 passes).
// BM=BN=128, BK=32. 8 warps as 4(m) x 2(n); warp tile 32x64.
// smem pitch 40 bf16 (80B) -> conflict-free ldmatrix.
// ---------------------------------------------------------------------------
#define LDT 40

__global__ __launch_bounds__(256) void k_gemm_mma(const float* __restrict__ X,
                                                  const float* __restrict__ W,
                                                  const float* __restrict__ bias) {
    __shared__ __align__(16) __nv_bfloat16 sAh[128 * LDT];
    __shared__ __align__(16) __nv_bfloat16 sAl[128 * LDT];
    __shared__ __align__(16) __nv_bfloat16 sBh[128 * LDT];
    __shared__ __align__(16) __nv_bfloat16 sBl[128 * LDT];

    const int tid = threadIdx.x, lane = tid & 31, wid = tid >> 5;
    const int m0 = blockIdx.y * 128, n0 = blockIdx.x * 128;
    const int wm = (wid >> 1) * 32, wn = (wid & 1) * 64;

    const uint32_t sAh_b = smem_u32(sAh), sAl_b = smem_u32(sAl);
    const uint32_t sBh_b = smem_u32(sBh), sBl_b = smem_u32(sBl);

    // ldmatrix per-lane byte offsets
    const int lr = lane & 15, kc = (lane >> 4) << 3;             // A: row, col
    const uint32_t a_l = (uint32_t)(((wm + lr) * LDT + kc) * 2);
    const int br = (lane & 7) + ((lane >> 4) << 3);              // B: row
    const int bk = ((lane >> 3) & 1) << 3;                       // B: col
    const uint32_t b_l = (uint32_t)(((wn + br) * LDT + bk) * 2);

    float acc[2][8][4];
#pragma unroll
    for (int i = 0; i < 2; i++)
#pragma unroll
        for (int j = 0; j < 8; j++)
#pragma unroll
            for (int q = 0; q < 4; q++) acc[i][j][q] = 0.f;

#pragma unroll 1
    for (int ch = 0; ch < 16; ch++) {
        const int k0 = ch * 32;
#pragma unroll
        for (int it = 0; it < 4; it++) {
            const int idx = it * 256 + tid;
            const int r = idx >> 3, c = idx & 7;
            uint2 hi, lo;
            float4 vx = *(const float4*)&X[(size_t)(m0 + r) * CC + k0 + c * 4];
            cvt2(vx, hi, lo);
            *(uint2*)&sAh[r * LDT + c * 4] = hi;
            *(uint2*)&sAl[r * LDT + c * 4] = lo;
            float4 vw = *(const float4*)&W[(size_t)(n0 + r) * CC + k0 + c * 4];
            cvt2(vw, hi, lo);
            *(uint2*)&sBh[r * LDT + c * 4] = hi;
            *(uint2*)&sBl[r * LDT + c * 4] = lo;
        }
        __syncthreads();

#pragma unroll
        for (int s = 0; s < 2; s++) {
            uint32_t Ah[2][4], Al[2][4];
#pragma unroll
            for (int i = 0; i < 2; i++) {
                const uint32_t off = a_l + (uint32_t)(i * 16 * LDT * 2 + s * 32);
                ldsm4(Ah[i], sAh_b + off);
                ldsm4(Al[i], sAl_b + off);
            }
#pragma unroll
            for (int g = 0; g < 4; g++) {
                const uint32_t off = b_l + (uint32_t)(g * 16 * LDT * 2 + s * 32);
                uint32_t Bh[4], Bl[4];
                ldsm4(Bh, sBh_b + off);
                ldsm4(Bl, sBl_b + off);
#pragma unroll
                for (int i = 0; i < 2; i++) {
                    mma16816(acc[i][2 * g],     Ah[i], Bh[0], Bh[1]);
                    mma16816(acc[i][2 * g + 1], Ah[i], Bh[2], Bh[3]);
                    mma16816(acc[i][2 * g],     Ah[i], Bl[0], Bl[1]);
                    mma16816(acc[i][2 * g + 1], Ah[i], Bl[2], Bl[3]);
                    mma16816(acc[i][2 * g],     Al[i], Bh[0], Bh[1]);
                    mma16816(acc[i][2 * g + 1], Al[i], Bh[2], Bh[3]);
                }
            }
        }
        __syncthreads();
    }

    // Epilogue: add bias, store fp32
    const int cr = lane >> 2, cc2 = (lane & 3) * 2;
#pragma unroll
    for (int i = 0; i < 2; i++) {
        const int m = m0 + wm + i * 16 + cr;
#pragma unroll
        for (int j = 0; j < 8; j++) {
            const int n = n0 + wn + j * 8 + cc2;
            float2 bv = *(const float2*)&bias[n];
            *(float2*)&g_wf[(size_t)m * CC + n] =
                make_float2(acc[i][j][0] + bv.x, acc[i][j][1] + bv.y);
            *(float2*)&g_wf[(size_t)(m + 8) * CC + n] =
                make_float2(acc[i][j][2] + bv.x, acc[i][j][3] + bv.y);
        }
    }
}

// ---------------------------------------------------------------------------
// Kernel 2: scores[b,l,t] = sum_c tanh(wf[b,t,c] + pos[l,c]) * aw[c]
// (atten_b dropped: softmax shift-invariant)
// ---------------------------------------------------------------------------
__device__ __forceinline__ float fast_tanh(float x) {
    x = fminf(15.f, fmaxf(-15.f, x));
    float e = __expf(2.f * x);
    return __fdividef(e - 1.f, e + 1.f);
}

__global__ __launch_bounds__(256) void k_scores(const float* __restrict__ pos,
                                                const float* __restrict__ aw) {
    __shared__ __align__(16) float sp[13 * CC];

    const int tid = threadIdx.x;
    const int b = blockIdx.x;
    const int tch = blockIdx.y;
    const int l0 = blockIdx.z * 13;
    const int nl = blockIdx.z ? 12 : 13;
    const int warp = tid >> 5, lane = tid & 31;

    for (int i = tid; i < nl * CC; i += 256) sp[i] = pos[l0 * CC + i];
    __syncthreads();

    float4 wv[4];
#pragma unroll
    for (int g = 0; g < 4; g++)
        wv[g] = *(const float4*)&aw[g * 128 + lane * 4];

    for (int tt = 0; tt < 4; tt++) {
        const int t = tch * 32 + warp * 4 + tt;
        const float* wrow = &g_wf[((size_t)b * TT + t) * CC];
        float4 fv[4];
#pragma unroll
        for (int g = 0; g < 4; g++)
            fv[g] = *(const float4*)&wrow[g * 128 + lane * 4];

        for (int l = 0; l < nl; l++) {
            float acc = 0.f;
#pragma unroll
            for (int g = 0; g < 4; g++) {
                float4 p = *(const float4*)&sp[l * CC + g * 128 + lane * 4];
                acc += fast_tanh(fv[g].x + p.x) * wv[g].x;
                acc += fast_tanh(fv[g].y + p.y) * wv[g].y;
                acc += fast_tanh(fv[g].z + p.z) * wv[g].z;
                acc += fast_tanh(fv[g].w + p.w) * wv[g].w;
            }
#pragma unroll
            for (int o = 16; o > 0; o >>= 1)
                acc += __shfl_xor_sync(0xFFFFFFFFu, acc, o);
            if (lane == 0)
                g_scores[((size_t)b * LL + l0 + l) * TT + t] = acc;
        }
    }
}

// ---------------------------------------------------------------------------
// Kernel 3: in-place softmax over t.
// ---------------------------------------------------------------------------
__global__ __launch_bounds__(256) void k_softmax() {
    __shared__ float red[8];
    __shared__ float red2[8];
    const int row = blockIdx.x;
    float* s = g_scores + (size_t)row * TT;
    const int tid = threadIdx.x, lane = tid & 31, w = tid >> 5;

    float v = s[tid];
    float m = v;
#pragma unroll
    for (int o = 16; o > 0; o >>= 1)
        m = fmaxf(m, __shfl_xor_sync(0xFFFFFFFFu, m, o));
    if (lane == 0) red[w] = m;
    __syncthreads();
    float bm = red[0];
#pragma unroll
    for (int i = 1; i < 8; i++) bm = fmaxf(bm, red[i]);

    float e = __expf(v - bm);
    float sum = e;
#pragma unroll
    for (int o = 16; o > 0; o >>= 1)
        sum += __shfl_xor_sync(0xFFFFFFFFu, sum, o);
    if (lane == 0) red2[w] = sum;
    __syncthreads();
    float tot = 0.f;
#pragma unroll
    for (int i = 0; i < 8; i++) tot += red2[i];

    s[tid] = e / tot;
}

// ---------------------------------------------------------------------------
// Kernel 4a: pvam split over t (4 ways) into partials. grid (4, B, 4).
// ---------------------------------------------------------------------------
__global__ __launch_bounds__(128) void k_pvam1() {
    __shared__ float at[LL][64];
    const int b = blockIdx.y, c0 = blockIdx.x * 128, s = blockIdx.z;
    const int tid = threadIdx.x;

    for (int i = tid; i < LL * 64; i += 128) {
        int l = i >> 6, j = i & 63;
        at[l][j] = g_scores[((size_t)b * LL + l) * TT + s * 64 + j];
    }
    __syncthreads();

    float acc[LL];
#pragma unroll
    for (int l = 0; l < LL; l++) acc[l] = 0.f;

    const float* wb = &g_wf[((size_t)b * TT + s * 64) * CC + c0 + tid];
#pragma unroll 4
    for (int j = 0; j < 64; j++) {
        float v = wb[(size_t)j * CC];
#pragma unroll
        for (int l = 0; l < LL; l++) acc[l] += at[l][j] * v;
    }

    float* pp = &g_part[(size_t)s * BB * LL * CC + (size_t)b * LL * CC + c0 + tid];
#pragma unroll
    for (int l = 0; l < LL; l++) pp[(size_t)l * CC] = acc[l];
}

// Kernel 4b: sum the 4 partials -> out.
__global__ __launch_bounds__(256) void k_pvam2(float* __restrict__ out) {
    const size_t N = (size_t)BB * LL * CC;
    size_t i = (size_t)blockIdx.x * 256 + threadIdx.x;
    out[i] = g_part[i] + g_part[N + i] + g_part[2 * N + i] + g_part[3 * N + i];
}

// ---------------------------------------------------------------------------
extern "C" void kernel_launch(void* const* d_in, const int* in_sizes, int n_in,
                              void* d_out, int out_size) {
    const float* X    = (const float*)d_in[0];
    const float* W    = (const float*)d_in[1];
    const float* bias = (const float*)d_in[2];
    const float* pos  = (const float*)d_in[3];
    const float* aw   = (const float*)d_in[4];
    float* out = (float*)d_out;

    k_gemm_mma<<<dim3(CC / 128, MM / 128), 256>>>(X, W, bias);
    k_scores<<<dim3(BB, TT / 32, 2), 256>>>(pos, aw);
    k_softmax<<<BB * LL, 256>>>();
    k_pvam1<<<dim3(CC / 128, BB, 4), 128>>>();
    k_pvam2<<<BB * LL * CC / 256, 256>>>(out);
}

// round 7
// speedup vs baseline: 1.7948x; 1.1055x over previous
#include <cuda_runtime.h>
#include <cuda_bf16.h>
#include <cstdint>

#define BB 32
#define TT 256
#define CC 512
#define LL 25
#define MM (BB*TT)   // 8192

// Scratch (device globals — no runtime allocation allowed)
__device__ float g_wf[(size_t)MM * CC];            // 16 MB
__device__ float g_scores[(size_t)BB * LL * TT];   // 0.8 MB
__device__ float g_part[(size_t)8 * BB * LL * CC]; // 13 MB pvam partials
__device__ __align__(16) __nv_bfloat16 g_Xh[(size_t)MM * CC];
__device__ __align__(16) __nv_bfloat16 g_Xl[(size_t)MM * CC];
__device__ __align__(16) __nv_bfloat16 g_Wh[(size_t)CC * CC];
__device__ __align__(16) __nv_bfloat16 g_Wl[(size_t)CC * CC];

// ---------------------------------------------------------------------------
// Helpers
// ---------------------------------------------------------------------------
__device__ __forceinline__ uint32_t smem_u32(const void* p) {
    uint32_t a;
    asm("{ .reg .u64 t; cvta.to.shared.u64 t, %1; cvt.u32.u64 %0, t; }"
        : "=r"(a) : "l"(p));
    return a;
}
__device__ __forceinline__ void ldsm4(uint32_t* r, uint32_t addr) {
    asm volatile("ldmatrix.sync.aligned.m8n8.x4.shared.b16 {%0,%1,%2,%3}, [%4];"
                 : "=r"(r[0]), "=r"(r[1]), "=r"(r[2]), "=r"(r[3]) : "r"(addr));
}
__device__ __forceinline__ void mma16816(float* d, const uint32_t* a,
                                         uint32_t b0, uint32_t b1) {
    asm volatile(
        "mma.sync.aligned.m16n8k16.row.col.f32.bf16.bf16.f32 "
        "{%0,%1,%2,%3}, {%4,%5,%6,%7}, {%8,%9}, {%0,%1,%2,%3};"
        : "+f"(d[0]), "+f"(d[1]), "+f"(d[2]), "+f"(d[3])
        : "r"(a[0]), "r"(a[1]), "r"(a[2]), "r"(a[3]), "r"(b0), "r"(b1));
}
// fp32 -> bf16 hi + bf16 lo (residual), packed as bf16x2 words
__device__ __forceinline__ void cvt2(float4 v, uint2& hi, uint2& lo) {
    __nv_bfloat162 h01 = __floats2bfloat162_rn(v.x, v.y);
    __nv_bfloat162 h23 = __floats2bfloat162_rn(v.z, v.w);
    float2 f01 = __bfloat1622float2(h01);
    float2 f23 = __bfloat1622float2(h23);
    __nv_bfloat162 l01 = __floats2bfloat162_rn(v.x - f01.x, v.y - f01.y);
    __nv_bfloat162 l23 = __floats2bfloat162_rn(v.z - f23.x, v.w - f23.y);
    hi.x = *reinterpret_cast<uint32_t*>(&h01);
    hi.y = *reinterpret_cast<uint32_t*>(&h23);
    lo.x = *reinterpret_cast<uint32_t*>(&l01);
    lo.y = *reinterpret_cast<uint32_t*>(&l23);
}

// ---------------------------------------------------------------------------
// Kernel 0: fp32 -> bf16 hi/lo prepass. Globals referenced IN DEVICE CODE
// (passing __device__ symbols from host gives the host shadow address, which
// ATS happily writes to — the R5/R6 bug).
// ---------------------------------------------------------------------------
__global__ __launch_bounds__(256) void k_cvtX(const float* __restrict__ src) {
    const size_t i = (size_t)blockIdx.x * 256 + threadIdx.x;
    float4 v = ((const float4*)src)[i];
    uint2 h, l;
    cvt2(v, h, l);
    ((uint2*)g_Xh)[i] = h;
    ((uint2*)g_Xl)[i] = l;
}
__global__ __launch_bounds__(256) void k_cvtW(const float* __restrict__ src) {
    const size_t i = (size_t)blockIdx.x * 256 + threadIdx.x;
    float4 v = ((const float4*)src)[i];
    uint2 h, l;
    cvt2(v, h, l);
    ((uint2*)g_Wh)[i] = h;
    ((uint2*)g_Wl)[i] = l;
}

// ---------------------------------------------------------------------------
// Kernel 1: wf = X @ W^T + bias via mma.sync bf16 hi/lo split (3 passes).
// R4-proven structure: BM=BN=128, BK=32, 8 warps 4(m)x2(n), warp tile 32x64,
// smem pitch LDT=40 bf16. Smem fill copies pre-converted bf16 (uint2 loads).
// ---------------------------------------------------------------------------
#define LDT 40

__global__ __launch_bounds__(256) void k_gemm_mma(const float* __restrict__ bias) {
    __shared__ __align__(16) __nv_bfloat16 sAh[128 * LDT];
    __shared__ __align__(16) __nv_bfloat16 sAl[128 * LDT];
    __shared__ __align__(16) __nv_bfloat16 sBh[128 * LDT];
    __shared__ __align__(16) __nv_bfloat16 sBl[128 * LDT];

    const int tid = threadIdx.x, lane = tid & 31, wid = tid >> 5;
    const int m0 = blockIdx.y * 128, n0 = blockIdx.x * 128;
    const int wm = (wid >> 1) * 32, wn = (wid & 1) * 64;

    const uint32_t sAh_b = smem_u32(sAh), sAl_b = smem_u32(sAl);
    const uint32_t sBh_b = smem_u32(sBh), sBl_b = smem_u32(sBl);

    // ldmatrix per-lane byte offsets (identical to R4)
    const int lr = lane & 15, kc = (lane >> 4) << 3;             // A: row, col
    const uint32_t a_l = (uint32_t)(((wm + lr) * LDT + kc) * 2);
    const int br = (lane & 7) + ((lane >> 4) << 3);              // B: row
    const int bk = ((lane >> 3) & 1) << 3;                       // B: col
    const uint32_t b_l = (uint32_t)(((wn + br) * LDT + bk) * 2);

    float acc[2][8][4];
#pragma unroll
    for (int i = 0; i < 2; i++)
#pragma unroll
        for (int j = 0; j < 8; j++)
#pragma unroll
            for (int q = 0; q < 4; q++) acc[i][j][q] = 0.f;

#pragma unroll 1
    for (int ch = 0; ch < 16; ch++) {
        const int k0 = ch * 32;
#pragma unroll
        for (int it = 0; it < 4; it++) {
            const int idx = it * 256 + tid;
            const int r = idx >> 3, c = idx & 7;      // row 0..127, col-chunk 0..7
            const size_t gx = (size_t)(m0 + r) * CC + k0 + c * 4;
            const size_t gw = (size_t)(n0 + r) * CC + k0 + c * 4;
            *(uint2*)&sAh[r * LDT + c * 4] = *(const uint2*)&g_Xh[gx];
            *(uint2*)&sAl[r * LDT + c * 4] = *(const uint2*)&g_Xl[gx];
            *(uint2*)&sBh[r * LDT + c * 4] = *(const uint2*)&g_Wh[gw];
            *(uint2*)&sBl[r * LDT + c * 4] = *(const uint2*)&g_Wl[gw];
        }
        __syncthreads();

#pragma unroll
        for (int s = 0; s < 2; s++) {
            uint32_t Ah[2][4], Al[2][4];
#pragma unroll
            for (int i = 0; i < 2; i++) {
                const uint32_t off = a_l + (uint32_t)(i * 16 * LDT * 2 + s * 32);
                ldsm4(Ah[i], sAh_b + off);
                ldsm4(Al[i], sAl_b + off);
            }
#pragma unroll
            for (int g = 0; g < 4; g++) {
                const uint32_t off = b_l + (uint32_t)(g * 16 * LDT * 2 + s * 32);
                uint32_t Bh[4], Bl[4];
                ldsm4(Bh, sBh_b + off);
                ldsm4(Bl, sBl_b + off);
#pragma unroll
                for (int i = 0; i < 2; i++) {
                    mma16816(acc[i][2 * g],     Ah[i], Bh[0], Bh[1]);
                    mma16816(acc[i][2 * g + 1], Ah[i], Bh[2], Bh[3]);
                    mma16816(acc[i][2 * g],     Ah[i], Bl[0], Bl[1]);
                    mma16816(acc[i][2 * g + 1], Ah[i], Bl[2], Bl[3]);
                    mma16816(acc[i][2 * g],     Al[i], Bh[0], Bh[1]);
                    mma16816(acc[i][2 * g + 1], Al[i], Bh[2], Bh[3]);
                }
            }
        }
        __syncthreads();
    }

    // Epilogue: add bias, store fp32
    const int cr = lane >> 2, cc2 = (lane & 3) * 2;
#pragma unroll
    for (int i = 0; i < 2; i++) {
        const int m = m0 + wm + i * 16 + cr;
#pragma unroll
        for (int j = 0; j < 8; j++) {
            const int n = n0 + wn + j * 8 + cc2;
            float2 bv = *(const float2*)&bias[n];
            *(float2*)&g_wf[(size_t)m * CC + n] =
                make_float2(acc[i][j][0] + bv.x, acc[i][j][1] + bv.y);
            *(float2*)&g_wf[(size_t)(m + 8) * CC + n] =
                make_float2(acc[i][j][2] + bv.x, acc[i][j][3] + bv.y);
        }
    }
}

// ---------------------------------------------------------------------------
// Kernel 2: scores[b,l,t] = sum_c tanh(wf[b,t,c] + pos[l,c]) * aw[c]
// HW tanh.approx (1 MUFU) — the lone experimental change being validated.
// atten_b dropped (softmax shift-invariant).
// ---------------------------------------------------------------------------
__device__ __forceinline__ float tanh_hw(float x) {
    float y;
    asm("tanh.approx.f32 %0, %1;" : "=f"(y) : "f"(x));
    return y;
}

__global__ __launch_bounds__(256) void k_scores(const float* __restrict__ pos,
                                                const float* __restrict__ aw) {
    __shared__ __align__(16) float sp[13 * CC];

    const int tid = threadIdx.x;
    const int b = blockIdx.x;
    const int tch = blockIdx.y;
    const int l0 = blockIdx.z * 13;
    const int nl = blockIdx.z ? 12 : 13;
    const int warp = tid >> 5, lane = tid & 31;

    for (int i = tid; i < nl * CC; i += 256) sp[i] = pos[l0 * CC + i];
    __syncthreads();

    float4 wv[4];
#pragma unroll
    for (int g = 0; g < 4; g++)
        wv[g] = *(const float4*)&aw[g * 128 + lane * 4];

    for (int tt = 0; tt < 4; tt++) {
        const int t = tch * 32 + warp * 4 + tt;
        const float* wrow = &g_wf[((size_t)b * TT + t) * CC];
        float4 fv[4];
#pragma unroll
        for (int g = 0; g < 4; g++)
            fv[g] = *(const float4*)&wrow[g * 128 + lane * 4];

        for (int l = 0; l < nl; l++) {
            float acc = 0.f;
#pragma unroll
            for (int g = 0; g < 4; g++) {
                float4 p = *(const float4*)&sp[l * CC + g * 128 + lane * 4];
                acc += tanh_hw(fv[g].x + p.x) * wv[g].x;
                acc += tanh_hw(fv[g].y + p.y) * wv[g].y;
                acc += tanh_hw(fv[g].z + p.z) * wv[g].z;
                acc += tanh_hw(fv[g].w + p.w) * wv[g].w;
            }
#pragma unroll
            for (int o = 16; o > 0; o >>= 1)
                acc += __shfl_xor_sync(0xFFFFFFFFu, acc, o);
            if (lane == 0)
                g_scores[((size_t)b * LL + l0 + l) * TT + t] = acc;
        }
    }
}

// ---------------------------------------------------------------------------
// Kernel 3: in-place softmax over t.
// ---------------------------------------------------------------------------
__global__ __launch_bounds__(256) void k_softmax() {
    __shared__ float red[8];
    __shared__ float red2[8];
    const int row = blockIdx.x;
    float* s = g_scores + (size_t)row * TT;
    const int tid = threadIdx.x, lane = tid & 31, w = tid >> 5;

    float v = s[tid];
    float m = v;
#pragma unroll
    for (int o = 16; o > 0; o >>= 1)
        m = fmaxf(m, __shfl_xor_sync(0xFFFFFFFFu, m, o));
    if (lane == 0) red[w] = m;
    __syncthreads();
    float bm = red[0];
#pragma unroll
    for (int i = 1; i < 8; i++) bm = fmaxf(bm, red[i]);

    float e = __expf(v - bm);
    float sum = e;
#pragma unroll
    for (int o = 16; o > 0; o >>= 1)
        sum += __shfl_xor_sync(0xFFFFFFFFu, sum, o);
    if (lane == 0) red2[w] = sum;
    __syncthreads();
    float tot = 0.f;
#pragma unroll
    for (int i = 0; i < 8; i++) tot += red2[i];

    s[tid] = e / tot;
}

// ---------------------------------------------------------------------------
// Kernel 4a: pvam split over t (8 ways) into partials. grid (4, B, 8).
// ---------------------------------------------------------------------------
__global__ __launch_bounds__(128) void k_pvam1() {
    __shared__ float at[LL][32];
    const int b = blockIdx.y, c0 = blockIdx.x * 128, s = blockIdx.z;
    const int tid = threadIdx.x;

    for (int i = tid; i < LL * 32; i += 128) {
        int l = i >> 5, j = i & 31;
        at[l][j] = g_scores[((size_t)b * LL + l) * TT + s * 32 + j];
    }
    __syncthreads();

    float acc[LL];
#pragma unroll
    for (int l = 0; l < LL; l++) acc[l] = 0.f;

    const float* wb = &g_wf[((size_t)b * TT + s * 32) * CC + c0 + tid];
#pragma unroll
    for (int j = 0; j < 32; j++) {
        float v = wb[(size_t)j * CC];
#pragma unroll
        for (int l = 0; l < LL; l++) acc[l] += at[l][j] * v;
    }

    float* pp = &g_part[(size_t)s * BB * LL * CC + (size_t)b * LL * CC + c0 + tid];
#pragma unroll
    for (int l = 0; l < LL; l++) pp[(size_t)l * CC] = acc[l];
}

// Kernel 4b: sum the 8 partials -> out.
__global__ __launch_bounds__(256) void k_pvam2(float* __restrict__ out) {
    const size_t N = (size_t)BB * LL * CC;
    size_t i = (size_t)blockIdx.x * 256 + threadIdx.x;
    float a = 0.f;
#pragma unroll
    for (int s = 0; s < 8; s++) a += g_part[s * N + i];
    out[i] = a;
}

// ---------------------------------------------------------------------------
extern "C" void kernel_launch(void* const* d_in, const int* in_sizes, int n_in,
                              void* d_out, int out_size) {
    const float* X    = (const float*)d_in[0];
    const float* W    = (const float*)d_in[1];
    const float* bias = (const float*)d_in[2];
    const float* pos  = (const float*)d_in[3];
    const float* aw   = (const float*)d_in[4];
    float* out = (float*)d_out;

    k_cvtX<<<MM * CC / 4 / 256, 256>>>(X);
    k_cvtW<<<CC * CC / 4 / 256, 256>>>(W);
    k_gemm_mma<<<dim3(CC / 128, MM / 128), 256>>>(bias);
    k_scores<<<dim3(BB, TT / 32, 2), 256>>>(pos, aw);
    k_softmax<<<BB * LL, 256>>>();
    k_pvam1<<<dim3(CC / 128, BB, 8), 128>>>();
    k_pvam2<<<BB * LL * CC / 256, 256>>>(out);
}